// round 3
// baseline (speedup 1.0000x reference)
#include <cuda_runtime.h>

// Scatter-add with sorted indices:
//   out = self_tensor; for i in [0,M): out[sorted_index[i], :] += value[i, :]
// D = 128 floats per row. Index buffer is int32 (JAX x64 disabled downcasts
// the reference's "int64" to int32).

#define DCOLS 128
#define ROWS_PER_WARP 32

__global__ void copy_kernel(const float4* __restrict__ src,
                            float4* __restrict__ dst, long n4) {
    long i = blockIdx.x * (long)blockDim.x + threadIdx.x;
    long stride = (long)gridDim.x * blockDim.x;
    for (; i < n4; i += stride) dst[i] = src[i];
}

__device__ __forceinline__ void flush_run(float* __restrict__ out,
                                          int cur, int lane,
                                          float4 acc, bool exclusive) {
    float* dst = out + (long)cur * DCOLS + lane * 4;
    if (exclusive) {
        float4 o = *reinterpret_cast<float4*>(dst);
        o.x += acc.x; o.y += acc.y; o.z += acc.z; o.w += acc.w;
        *reinterpret_cast<float4*>(dst) = o;
    } else {
        atomicAdd(dst + 0, acc.x);
        atomicAdd(dst + 1, acc.y);
        atomicAdd(dst + 2, acc.z);
        atomicAdd(dst + 3, acc.w);
    }
}

__global__ void scatter_add_kernel(const float* __restrict__ value,
                                   const int* __restrict__ index,
                                   float* __restrict__ out, int M) {
    int gwarp = (int)((blockIdx.x * (long)blockDim.x + threadIdx.x) >> 5);
    int lane = threadIdx.x & 31;
    long start = (long)gwarp * ROWS_PER_WARP;
    if (start >= M) return;
    int rows = (int)min((long)ROWS_PER_WARP, (long)M - start);

    // Each lane loads one row's index; shfl broadcasts per-row.
    int myidx = (start + lane < (long)M) ? index[start + lane] : -1;
    // Runs fully inside this warp's 32-row chunk are exclusively owned
    // (indices are sorted); only runs touching a chunk edge need atomics.
    int idx_prev = (start > 0) ? index[start - 1] : -1;
    int idx_next = (start + ROWS_PER_WARP < (long)M)
                       ? index[start + ROWS_PER_WARP] : -1;

    const float4* vbase = reinterpret_cast<const float4*>(value)
                          + start * (DCOLS / 4) + lane;

    int cur = -1;
    float4 acc = make_float4(0.f, 0.f, 0.f, 0.f);
    bool have = false;

    for (int r = 0; r < rows; ++r) {
        int idx = __shfl_sync(0xffffffffu, myidx, r);
        float4 v = vbase[(long)r * (DCOLS / 4)];
        if (have && idx == cur) {
            acc.x += v.x; acc.y += v.y; acc.z += v.z; acc.w += v.w;
        } else {
            if (have)
                flush_run(out, cur, lane, acc,
                          (cur != idx_prev) && (cur != idx_next));
            cur = idx;
            acc = v;
            have = true;
        }
    }
    if (have)
        flush_run(out, cur, lane, acc,
                  (cur != idx_prev) && (cur != idx_next));
}

extern "C" void kernel_launch(void* const* d_in, const int* in_sizes, int n_in,
                              void* d_out, int out_size) {
    const float* self_tensor = (const float*)d_in[0];
    const float* value = (const float*)d_in[1];
    const int* sorted_index = (const int*)d_in[2];
    // d_in[3] = pos, unused.
    float* out = (float*)d_out;

    int M = in_sizes[2];            // number of scattered rows
    long n4 = (long)out_size / 4;   // out_size = N*D floats

    // 1) out = self_tensor
    {
        int threads = 256;
        long blocks = (n4 + threads - 1) / threads;
        if (blocks > 32768) blocks = 32768;
        copy_kernel<<<(int)blocks, threads>>>(
            (const float4*)self_tensor, (float4*)out, n4);
    }

    // 2) scatter-add value rows (same stream -> ordered after copy)
    {
        int warps = (M + ROWS_PER_WARP - 1) / ROWS_PER_WARP;
        int threads = 256;
        int blocks = (warps * 32 + threads - 1) / threads;
        scatter_add_kernel<<<blocks, threads>>>(value, sorted_index, out, M);
    }
}